// round 1
// baseline (speedup 1.0000x reference)
#include <cuda_runtime.h>
#include <math.h>

#define N_NODES 50000
#define N_EDGES 800000
#define MUL 32
#define RAD 8
#define FC 64
#define TILE 32
#define EDGE_BLOCKS 1184
#define N_TILES (N_EDGES / TILE)

// ---------------- scratch (static device globals; no allocation) ----------------
__device__ __align__(16) float g_f0[N_NODES * MUL];          // 6.4 MB
__device__ __align__(16) float g_self0[N_NODES * MUL];       // 6.4 MB
__device__ __align__(16) float g_f1[N_NODES * MUL * 3];      // 19.2 MB
__device__ __align__(16) float g_self1[N_NODES * MUL * 3];   // 19.2 MB
__device__ __align__(16) float g_n0[N_NODES * 2 * MUL];      // 12.8 MB
__device__ __align__(16) float g_n1[N_NODES * 2 * MUL * 3];  // 38.4 MB

__device__ __forceinline__ float gelu_f(float x) {
    // jax.nn.gelu default (approximate=True): tanh approximation
    float x3 = x * x * x;
    float t = tanhf(0.7978845608028654f * (x + 0.044715f * x3));
    return 0.5f * x * (1.0f + t);
}

__device__ __forceinline__ void red_add_v4(float* addr, float a, float b, float c, float d) {
    asm volatile("red.global.add.v4.f32 [%0], {%1,%2,%3,%4};"
                 :: "l"(addr), "f"(a), "f"(b), "f"(c), "f"(d) : "memory");
}

// ---------------- kernel 0: zero accumulators ----------------
__global__ void zero_acc_kernel() {
    int i = blockIdx.x * blockDim.x + threadIdx.x;
    float4 z = make_float4(0.f, 0.f, 0.f, 0.f);
    if (i < N_NODES * 16) reinterpret_cast<float4*>(g_n0)[i] = z;   // 64 floats/node
    if (i < N_NODES * 48) reinterpret_cast<float4*>(g_n1)[i] = z;   // 192 floats/node
}

// ---------------- kernel 1: node pre-transform ----------------
// f0 = node_s @ W_feat0 * ism ; self0 = node_s @ W_self0 * ism
// f1[n][v][i] = sum_u node_v[n][u][i] * W_feat1[u][v] * ism ; self1 likewise
__global__ __launch_bounds__(128) void node_transform_kernel(
    const float* __restrict__ node_s, const float* __restrict__ node_v,
    const float* __restrict__ Wf0, const float* __restrict__ Ws0,
    const float* __restrict__ Wf1, const float* __restrict__ Ws1)
{
    __shared__ float sWf0[MUL * MUL], sWs0[MUL * MUL], sWf1[MUL * MUL], sWs1[MUL * MUL];
    __shared__ float sS[4][MUL];
    __shared__ float sV[4][MUL * 3];
    int t = threadIdx.x;
    for (int i = t; i < MUL * MUL; i += 128) {
        sWf0[i] = Wf0[i]; sWs0[i] = Ws0[i]; sWf1[i] = Wf1[i]; sWs1[i] = Ws1[i];
    }
    int node0 = blockIdx.x * 4;
    int ni = t >> 5, j = t & 31;
    int n = node0 + ni;
    sS[ni][j] = node_s[n * MUL + j];
#pragma unroll
    for (int i = 0; i < 3; i++) sV[ni][j * 3 + i] = node_v[n * MUL * 3 + j * 3 + i];
    __syncthreads();

    float a0 = 0.f, b0 = 0.f;
    float a1x = 0.f, a1y = 0.f, a1z = 0.f, b1x = 0.f, b1y = 0.f, b1z = 0.f;
#pragma unroll
    for (int u = 0; u < MUL; ++u) {
        float su = sS[ni][u];
        float vx = sV[ni][u * 3 + 0], vy = sV[ni][u * 3 + 1], vz = sV[ni][u * 3 + 2];
        float wf0 = sWf0[u * MUL + j], ws0 = sWs0[u * MUL + j];
        float wf1 = sWf1[u * MUL + j], ws1 = sWs1[u * MUL + j];
        a0 += su * wf0;  b0 += su * ws0;
        a1x += vx * wf1; a1y += vy * wf1; a1z += vz * wf1;
        b1x += vx * ws1; b1y += vy * ws1; b1z += vz * ws1;
    }
    const float ism = 0.17677669529663687f; // 1/sqrt(32)
    g_f0[n * MUL + j]    = a0 * ism;
    g_self0[n * MUL + j] = b0 * ism;
    int vb = (n * MUL + j) * 3;
    g_f1[vb + 0] = a1x * ism; g_f1[vb + 1] = a1y * ism; g_f1[vb + 2] = a1z * ism;
    g_self1[vb + 0] = b1x * ism; g_self1[vb + 1] = b1y * ism; g_self1[vb + 2] = b1z * ism;
}

// ---------------- kernel 2: edge MLP + tensor product + scatter ----------------
// dynamic smem layout (floats):
//  sW0   [8][64]        @ 0      (512)
//  sW1T  [64][68]       @ 512    (4352)   mlp_w1 transposed, padded
//  sWPT  [128][68]      @ 4864   (8704)   wp0..wp3 transposed, padded
//  sH1   [32][68]       @ 13568  (2176)
//  sH2   [32][68]       @ 15744  (2176)
//  sWW   [32][132]      @ 17920  (4224)   per-edge w0..w3 (128 each row)
//  sES   [32][8]        @ 22144  (256)
//  sSh1  [32][4]        @ 22400  (128)
//  sSh0  [32]           @ 22528  (32)
//  sSrc  [32] (int)     @ 22560  (32)
//  sDst  [32] (int)     @ 22592  (32)
// total 22624 floats = 90496 bytes
#define EDGE_SMEM_FLOATS 22624
#define EDGE_SMEM_BYTES  (EDGE_SMEM_FLOATS * 4)

__global__ __launch_bounds__(128, 2) void edge_kernel(
    const float* __restrict__ sh0, const float* __restrict__ sh1,
    const float* __restrict__ edge_scalar,
    const int* __restrict__ edge_src, const int* __restrict__ edge_dst,
    const float* __restrict__ mlp_w0, const float* __restrict__ mlp_w1,
    const float* __restrict__ wp0, const float* __restrict__ wp1,
    const float* __restrict__ wp2, const float* __restrict__ wp3)
{
    extern __shared__ float smem[];
    float* sW0  = smem;
    float* sW1T = smem + 512;
    float* sWPT = smem + 4864;
    float* sH1  = smem + 13568;
    float* sH2  = smem + 15744;
    float* sWW  = smem + 17920;
    float* sES  = smem + 22144;
    float* sSh1 = smem + 22400;
    float* sSh0 = smem + 22528;
    int*   sSrc = (int*)(smem + 22560);
    int*   sDst = (int*)(smem + 22592);

    int t = threadIdx.x;

    // ---- load weights once per block ----
    for (int i = t; i < RAD * FC; i += 128) sW0[i] = mlp_w0[i];
    for (int i = t; i < FC * FC; i += 128) {
        int k = i / FC, j = i % FC;
        sW1T[j * 68 + k] = mlp_w1[i];
    }
    for (int i = t; i < FC * MUL; i += 128) {
        int k = i / MUL, m = i % MUL;
        sWPT[(m)      * 68 + k] = wp0[i];
        sWPT[(32 + m) * 68 + k] = wp1[i];
        sWPT[(64 + m) * 68 + k] = wp2[i];
        sWPT[(96 + m) * 68 + k] = wp3[i];
    }

    const float isr = 0.35355339059327373f; // 1/sqrt(8)
    const float isf = 0.125f;               // 1/sqrt(64)

    for (int tile = blockIdx.x; tile < N_TILES; tile += gridDim.x) {
        __syncthreads(); // previous tile's stage-4 reads done before overwrite
        int ebase = tile * TILE;

        // ---- load per-edge data ----
        if (t < TILE) {
            sSrc[t] = edge_src[ebase + t];
            sDst[t] = edge_dst[ebase + t];
            sSh0[t] = sh0[ebase + t];
            sSh1[t * 4 + 0] = sh1[(ebase + t) * 3 + 0];
            sSh1[t * 4 + 1] = sh1[(ebase + t) * 3 + 1];
            sSh1[t * 4 + 2] = sh1[(ebase + t) * 3 + 2];
        }
        for (int i = t; i < TILE * RAD; i += 128) sES[i] = edge_scalar[ebase * RAD + i];
        __syncthreads();

        // ---- stage 1: H1 = gelu(ES @ W0 * isr)   (32e x 64j, K=8) ----
        {
            int et = t >> 4, jt = t & 15;
            float acc[4][4];
#pragma unroll
            for (int x = 0; x < 4; x++)
#pragma unroll
                for (int y = 0; y < 4; y++) acc[x][y] = 0.f;
#pragma unroll
            for (int k = 0; k < RAD; k++) {
                float a[4], b[4];
#pragma unroll
                for (int x = 0; x < 4; x++) a[x] = sES[(et * 4 + x) * 8 + k];
#pragma unroll
                for (int y = 0; y < 4; y++) b[y] = sW0[k * 64 + jt * 4 + y];
#pragma unroll
                for (int x = 0; x < 4; x++)
#pragma unroll
                    for (int y = 0; y < 4; y++) acc[x][y] += a[x] * b[y];
            }
#pragma unroll
            for (int x = 0; x < 4; x++)
#pragma unroll
                for (int y = 0; y < 4; y++)
                    sH1[(et * 4 + x) * 68 + jt * 4 + y] = gelu_f(acc[x][y] * isr);
        }
        __syncthreads();

        // ---- stage 2: H2 = gelu(H1 @ W1 * isf)   (32e x 64j, K=64) ----
        {
            int et = t >> 4, jt = t & 15;
            float acc[4][4];
#pragma unroll
            for (int x = 0; x < 4; x++)
#pragma unroll
                for (int y = 0; y < 4; y++) acc[x][y] = 0.f;
#pragma unroll
            for (int kk = 0; kk < FC; kk += 4) {
                float4 a[4], b[4];
#pragma unroll
                for (int x = 0; x < 4; x++)
                    a[x] = *(const float4*)&sH1[(et * 4 + x) * 68 + kk];
#pragma unroll
                for (int y = 0; y < 4; y++)
                    b[y] = *(const float4*)&sW1T[(jt * 4 + y) * 68 + kk];
#pragma unroll
                for (int x = 0; x < 4; x++)
#pragma unroll
                    for (int y = 0; y < 4; y++)
                        acc[x][y] += a[x].x * b[y].x + a[x].y * b[y].y
                                   + a[x].z * b[y].z + a[x].w * b[y].w;
            }
#pragma unroll
            for (int x = 0; x < 4; x++)
#pragma unroll
                for (int y = 0; y < 4; y++)
                    sH2[(et * 4 + x) * 68 + jt * 4 + y] = gelu_f(acc[x][y] * isf);
        }
        __syncthreads();

        // ---- stage 3: W = H2 @ [wp0|wp1|wp2|wp3] * isf   (32e x 128m, K=64) ----
        {
            int et = t >> 4, mt = t & 15;
            float acc[4][8];
#pragma unroll
            for (int x = 0; x < 4; x++)
#pragma unroll
                for (int y = 0; y < 8; y++) acc[x][y] = 0.f;
#pragma unroll
            for (int kk = 0; kk < FC; kk += 4) {
                float4 a[4];
#pragma unroll
                for (int x = 0; x < 4; x++)
                    a[x] = *(const float4*)&sH2[(et * 4 + x) * 68 + kk];
                float4 b[8];
#pragma unroll
                for (int y = 0; y < 8; y++)
                    b[y] = *(const float4*)&sWPT[(mt * 8 + y) * 68 + kk];
#pragma unroll
                for (int x = 0; x < 4; x++)
#pragma unroll
                    for (int y = 0; y < 8; y++)
                        acc[x][y] += a[x].x * b[y].x + a[x].y * b[y].y
                                   + a[x].z * b[y].z + a[x].w * b[y].w;
            }
#pragma unroll
            for (int x = 0; x < 4; x++)
#pragma unroll
                for (int y = 0; y < 8; y++)
                    sWW[(et * 4 + x) * 132 + mt * 8 + y] = acc[x][y] * isf;
        }
        __syncthreads();

        // ---- stage 4: gather f0/f1[src], tensor product, v4-red scatter ----
        {
            int e = t >> 2;
            int q = t & 3;
            int src = sSrc[e];
            int dst = sDst[e];
            float s0 = sSh0[e];
            float s1x = sSh1[e * 4 + 0], s1y = sSh1[e * 4 + 1], s1z = sSh1[e * 4 + 2];
            int u0 = q * 8;

            float e0v[8];
            {
                float4 A = *(const float4*)&g_f0[src * 32 + u0];
                float4 B = *(const float4*)&g_f0[src * 32 + u0 + 4];
                e0v[0] = A.x; e0v[1] = A.y; e0v[2] = A.z; e0v[3] = A.w;
                e0v[4] = B.x; e0v[5] = B.y; e0v[6] = B.z; e0v[7] = B.w;
            }
            float e1v[24];
            {
                const float4* p = (const float4*)&g_f1[src * 96 + u0 * 3];
#pragma unroll
                for (int i = 0; i < 6; i++) {
                    float4 v = p[i];
                    e1v[4 * i + 0] = v.x; e1v[4 * i + 1] = v.y;
                    e1v[4 * i + 2] = v.z; e1v[4 * i + 3] = v.w;
                }
            }
            float w0v[8], w1v[8], w2v[8], w3v[8];
#pragma unroll
            for (int x = 0; x < 8; x++) {
                w0v[x] = sWW[e * 132 + 0  + u0 + x];
                w1v[x] = sWW[e * 132 + 32 + u0 + x];
                w2v[x] = sWW[e * 132 + 64 + u0 + x];
                w3v[x] = sWW[e * 132 + 96 + u0 + x];
            }
            const float inn = 0.25f;                       // 1/sqrt(16)
            const float k3  = 0.5773502691896258f * 0.25f; // INV_SQRT3 * inn
            float p0[8], p3[8], p1[24], p2[24];
#pragma unroll
            for (int x = 0; x < 8; x++) {
                float e0u = e0v[x];
                float ex = e1v[3 * x + 0], ey = e1v[3 * x + 1], ez = e1v[3 * x + 2];
                p0[x] = w0v[x] * e0u * s0 * inn;
                p3[x] = w3v[x] * (ex * s1x + ey * s1y + ez * s1z) * k3;
                float w1e = w1v[x] * e0u * inn;
                p1[3 * x + 0] = w1e * s1x; p1[3 * x + 1] = w1e * s1y; p1[3 * x + 2] = w1e * s1z;
                float w2s = w2v[x] * s0 * inn;
                p2[3 * x + 0] = w2s * ex; p2[3 * x + 1] = w2s * ey; p2[3 * x + 2] = w2s * ez;
            }
            float* n0a = &g_n0[dst * 64 + u0];
            red_add_v4(n0a,     p0[0], p0[1], p0[2], p0[3]);
            red_add_v4(n0a + 4, p0[4], p0[5], p0[6], p0[7]);
            float* n0b = &g_n0[dst * 64 + 32 + u0];
            red_add_v4(n0b,     p3[0], p3[1], p3[2], p3[3]);
            red_add_v4(n0b + 4, p3[4], p3[5], p3[6], p3[7]);
            float* n1a = &g_n1[dst * 192 + u0 * 3];
#pragma unroll
            for (int i = 0; i < 6; i++)
                red_add_v4(n1a + 4 * i, p1[4 * i], p1[4 * i + 1], p1[4 * i + 2], p1[4 * i + 3]);
            float* n1b = &g_n1[dst * 192 + 96 + u0 * 3];
#pragma unroll
            for (int i = 0; i < 6; i++)
                red_add_v4(n1b + 4 * i, p2[4 * i], p2[4 * i + 1], p2[4 * i + 2], p2[4 * i + 3]);
        }
    }
}

// ---------------- kernel 3: output transform ----------------
__global__ __launch_bounds__(128) void output_kernel(
    const float* __restrict__ Wout0, const float* __restrict__ Wout1,
    float* __restrict__ out)
{
    __shared__ float sW0[FC * MUL], sW1[FC * MUL];
    __shared__ float sN0[4][64];
    __shared__ float sN1[4][192];
    int t = threadIdx.x;
    for (int i = t; i < FC * MUL; i += 128) { sW0[i] = Wout0[i]; sW1[i] = Wout1[i]; }
    int node0 = blockIdx.x * 4;
    for (int i = t; i < 4 * 64; i += 128)  sN0[i / 64][i % 64]   = g_n0[node0 * 64 + i];
    for (int i = t; i < 4 * 192; i += 128) sN1[i / 192][i % 192] = g_n1[node0 * 192 + i];
    __syncthreads();

    int ni = t >> 5, j = t & 31;
    int n = node0 + ni;
    float c0 = 0.f, c1x = 0.f, c1y = 0.f, c1z = 0.f;
#pragma unroll
    for (int u = 0; u < FC; u++) {
        float w0 = sW0[u * 32 + j], w1 = sW1[u * 32 + j];
        c0  += sN0[ni][u] * w0;
        c1x += sN1[ni][u * 3 + 0] * w1;
        c1y += sN1[ni][u * 3 + 1] * w1;
        c1z += sN1[ni][u * 3 + 2] * w1;
    }
    const float i2m = 0.125f; // 1/sqrt(64)
    const float cc = 0.9238795325112867f;  // cos(pi/8)
    const float ss = 0.3826834323650898f;  // sin(pi/8)
    int vb = (n * 32 + j) * 3;
    float o0  = cc * g_self0[n * 32 + j] + ss * c0 * i2m;
    float o1x = cc * g_self1[vb + 0] + ss * c1x * i2m;
    float o1y = cc * g_self1[vb + 1] + ss * c1y * i2m;
    float o1z = cc * g_self1[vb + 2] + ss * c1z * i2m;
    out[n * 128 + j] = o0;
    out[n * 128 + 32 + j * 3 + 0] = o1x;
    out[n * 128 + 32 + j * 3 + 1] = o1y;
    out[n * 128 + 32 + j * 3 + 2] = o1z;
}

// ---------------- host launcher ----------------
extern "C" void kernel_launch(void* const* d_in, const int* in_sizes, int n_in,
                              void* d_out, int out_size)
{
    const float* node_s      = (const float*)d_in[0];
    const float* node_v      = (const float*)d_in[1];
    const float* sh0         = (const float*)d_in[2];
    const float* sh1         = (const float*)d_in[3];
    const float* edge_scalar = (const float*)d_in[4];
    const int*   edge_src    = (const int*)d_in[5];
    const int*   edge_dst    = (const int*)d_in[6];
    const float* W_feat0     = (const float*)d_in[7];
    const float* W_self0     = (const float*)d_in[8];
    const float* W_feat1     = (const float*)d_in[9];
    const float* W_self1     = (const float*)d_in[10];
    const float* mlp_w0      = (const float*)d_in[11];
    const float* mlp_w1      = (const float*)d_in[12];
    const float* wp0         = (const float*)d_in[13];
    const float* wp1         = (const float*)d_in[14];
    const float* wp2         = (const float*)d_in[15];
    const float* wp3         = (const float*)d_in[16];
    const float* W_out0      = (const float*)d_in[17];
    const float* W_out1      = (const float*)d_in[18];
    float* out = (float*)d_out;

    cudaFuncSetAttribute(edge_kernel, cudaFuncAttributeMaxDynamicSharedMemorySize,
                         EDGE_SMEM_BYTES);

    // zero the scatter accumulators (9375 blocks cover the larger array)
    zero_acc_kernel<<<(N_NODES * 48 + 255) / 256, 256>>>();

    node_transform_kernel<<<N_NODES / 4, 128>>>(node_s, node_v,
                                                W_feat0, W_self0, W_feat1, W_self1);

    edge_kernel<<<EDGE_BLOCKS, 128, EDGE_SMEM_BYTES>>>(
        sh0, sh1, edge_scalar, edge_src, edge_dst,
        mlp_w0, mlp_w1, wp0, wp1, wp2, wp3);

    output_kernel<<<N_NODES / 4, 128>>>(W_out0, W_out1, out);
}

// round 2
// speedup vs baseline: 2.6758x; 2.6758x over previous
#include <cuda_runtime.h>
#include <math.h>

#define N_NODES 50000
#define N_EDGES 800000
#define MUL 32
#define RAD 8
#define FC 64
#define TILE 32
#define EDGE_BLOCKS 592
#define N_TILES (N_EDGES / TILE)

// ---------------- scratch (static device globals; no allocation) ----------------
__device__ __align__(16) float g_f0[N_NODES * MUL];          // 6.4 MB
__device__ __align__(16) float g_self0[N_NODES * MUL];       // 6.4 MB
__device__ __align__(16) float g_f1[N_NODES * MUL * 3];      // 19.2 MB
__device__ __align__(16) float g_self1[N_NODES * MUL * 3];   // 19.2 MB
__device__ __align__(16) float g_n0[N_NODES * 2 * MUL];      // 12.8 MB
__device__ __align__(16) float g_n1[N_NODES * 2 * MUL * 3];  // 38.4 MB

__device__ __forceinline__ float gelu_f(float x) {
    // tanh-approx gelu (jax.nn.gelu approximate=True); tanh.approx.f32 is 1 MUFU op
    float u = 0.7978845608028654f * fmaf(0.044715f * x, x * x, x);
    float t;
    asm("tanh.approx.f32 %0, %1;" : "=f"(t) : "f"(u));
    return 0.5f * x * (1.0f + t);
}

__device__ __forceinline__ void red_add_v4(float* addr, float a, float b, float c, float d) {
    asm volatile("red.global.add.v4.f32 [%0], {%1,%2,%3,%4};"
                 :: "l"(addr), "f"(a), "f"(b), "f"(c), "f"(d) : "memory");
}

// ---------------- kernel 0: zero accumulators ----------------
__global__ void zero_acc_kernel() {
    int i = blockIdx.x * blockDim.x + threadIdx.x;
    float4 z = make_float4(0.f, 0.f, 0.f, 0.f);
    if (i < N_NODES * 16) reinterpret_cast<float4*>(g_n0)[i] = z;   // 64 floats/node
    if (i < N_NODES * 48) reinterpret_cast<float4*>(g_n1)[i] = z;   // 192 floats/node
}

// ---------------- kernel 1: node pre-transform ----------------
__global__ __launch_bounds__(128) void node_transform_kernel(
    const float* __restrict__ node_s, const float* __restrict__ node_v,
    const float* __restrict__ Wf0, const float* __restrict__ Ws0,
    const float* __restrict__ Wf1, const float* __restrict__ Ws1)
{
    __shared__ float sWf0[MUL * MUL], sWs0[MUL * MUL], sWf1[MUL * MUL], sWs1[MUL * MUL];
    __shared__ float sS[4][MUL];
    __shared__ float sV[4][MUL * 3];
    int t = threadIdx.x;
    for (int i = t; i < MUL * MUL; i += 128) {
        sWf0[i] = Wf0[i]; sWs0[i] = Ws0[i]; sWf1[i] = Wf1[i]; sWs1[i] = Ws1[i];
    }
    int node0 = blockIdx.x * 4;
    int ni = t >> 5, j = t & 31;
    int n = node0 + ni;
    sS[ni][j] = node_s[n * MUL + j];
#pragma unroll
    for (int i = 0; i < 3; i++) sV[ni][j * 3 + i] = node_v[n * MUL * 3 + j * 3 + i];
    __syncthreads();

    float a0 = 0.f, b0 = 0.f;
    float a1x = 0.f, a1y = 0.f, a1z = 0.f, b1x = 0.f, b1y = 0.f, b1z = 0.f;
#pragma unroll
    for (int u = 0; u < MUL; ++u) {
        float su = sS[ni][u];
        float vx = sV[ni][u * 3 + 0], vy = sV[ni][u * 3 + 1], vz = sV[ni][u * 3 + 2];
        float wf0 = sWf0[u * MUL + j], ws0 = sWs0[u * MUL + j];
        float wf1 = sWf1[u * MUL + j], ws1 = sWs1[u * MUL + j];
        a0 += su * wf0;  b0 += su * ws0;
        a1x += vx * wf1; a1y += vy * wf1; a1z += vz * wf1;
        b1x += vx * ws1; b1y += vy * ws1; b1z += vz * ws1;
    }
    const float ism = 0.17677669529663687f; // 1/sqrt(32)
    g_f0[n * MUL + j]    = a0 * ism;
    g_self0[n * MUL + j] = b0 * ism;
    int vb = (n * MUL + j) * 3;
    g_f1[vb + 0] = a1x * ism; g_f1[vb + 1] = a1y * ism; g_f1[vb + 2] = a1z * ism;
    g_self1[vb + 0] = b1x * ism; g_self1[vb + 1] = b1y * ism; g_self1[vb + 2] = b1z * ism;
}

// ---------------- kernel 2: edge MLP + tensor product + scatter ----------------
// dynamic smem (floats):
//  sW0   [8][64]          @ 0      (512)
//  sW1v  [16][260]        @ 512    (4160)  mlp_w1, k-major per 4-col group, pad 4
//  sWPv  [16][516]        @ 4672   (8256)  wp0..3, k-major per 8-col group, pad 4
//  sH1   [32][68]         @ 12928  (2176)
//  sH2   [32][68]         @ 15104  (2176)
//  sWW   [32][132]        @ 17280  (4224)
//  sES   [32][8]          @ 21504  (256)
// total 21760 floats = 87040 bytes
#define EDGE_SMEM_FLOATS 21760
#define EDGE_SMEM_BYTES  (EDGE_SMEM_FLOATS * 4)

__global__ __launch_bounds__(128, 2) void edge_kernel(
    const float* __restrict__ sh0, const float* __restrict__ sh1,
    const float* __restrict__ edge_scalar,
    const int* __restrict__ edge_src, const int* __restrict__ edge_dst,
    const float* __restrict__ mlp_w0, const float* __restrict__ mlp_w1,
    const float* __restrict__ wp0, const float* __restrict__ wp1,
    const float* __restrict__ wp2, const float* __restrict__ wp3)
{
    extern __shared__ float smem[];
    float* sW0  = smem;
    float* sW1v = smem + 512;
    float* sWPv = smem + 4672;
    float* sH1  = smem + 12928;
    float* sH2  = smem + 15104;
    float* sWW  = smem + 17280;
    float* sES  = smem + 21504;

    int t = threadIdx.x;

    // ---- load weights once per block (conflict-free layouts) ----
    for (int i = t; i < RAD * FC; i += 128) sW0[i] = mlp_w0[i];
    for (int i = t; i < FC * FC; i += 128) {
        int k = i >> 6, j = i & 63;
        sW1v[(j >> 2) * 260 + k * 4 + (j & 3)] = mlp_w1[i];
    }
    for (int i = t; i < FC * MUL; i += 128) {
        int k = i >> 5, m = i & 31;
        int c;
        c = m;      sWPv[(c >> 3) * 516 + k * 8 + (c & 7)] = wp0[i];
        c = 32 + m; sWPv[(c >> 3) * 516 + k * 8 + (c & 7)] = wp1[i];
        c = 64 + m; sWPv[(c >> 3) * 516 + k * 8 + (c & 7)] = wp2[i];
        c = 96 + m; sWPv[(c >> 3) * 516 + k * 8 + (c & 7)] = wp3[i];
    }

    const float isr = 0.35355339059327373f; // 1/sqrt(8)
    const float isf = 0.125f;               // 1/sqrt(64)

    int et = t >> 4, jt = t & 15;           // stage 1-3 mapping
    int e4 = t >> 2, q4 = t & 3;            // stage 4 mapping
    int u0 = q4 * 8;

    for (int tile = blockIdx.x; tile < N_TILES; tile += gridDim.x) {
        int ebase = tile * TILE;

        // ---- prefetch stage-4 operands from global (hidden behind stages 1-3) ----
        int src = edge_src[ebase + e4];
        int dst = edge_dst[ebase + e4];
        float s0  = sh0[ebase + e4];
        float s1x = sh1[(ebase + e4) * 3 + 0];
        float s1y = sh1[(ebase + e4) * 3 + 1];
        float s1z = sh1[(ebase + e4) * 3 + 2];
        float4 F0a = *(const float4*)&g_f0[src * 32 + u0];
        float4 F0b = *(const float4*)&g_f0[src * 32 + u0 + 4];
        float4 F1[6];
        {
            const float4* p = (const float4*)&g_f1[src * 96 + u0 * 3];
#pragma unroll
            for (int i = 0; i < 6; i++) F1[i] = p[i];
        }

        // ---- load per-edge scalars to smem ----
        for (int i = t; i < TILE * RAD; i += 128) sES[i] = edge_scalar[ebase * RAD + i];
        __syncthreads();

        // ---- stage 1: H1 = gelu(ES @ W0 * isr)   (32e x 64j, K=8) ----
        {
            float acc[4][4];
#pragma unroll
            for (int x = 0; x < 4; x++)
#pragma unroll
                for (int y = 0; y < 4; y++) acc[x][y] = 0.f;
#pragma unroll
            for (int k = 0; k < RAD; k++) {
                float4 b = *(const float4*)&sW0[k * 64 + jt * 4];
                float a[4];
#pragma unroll
                for (int x = 0; x < 4; x++) a[x] = sES[(et * 4 + x) * 8 + k];
#pragma unroll
                for (int x = 0; x < 4; x++) {
                    acc[x][0] = fmaf(a[x], b.x, acc[x][0]);
                    acc[x][1] = fmaf(a[x], b.y, acc[x][1]);
                    acc[x][2] = fmaf(a[x], b.z, acc[x][2]);
                    acc[x][3] = fmaf(a[x], b.w, acc[x][3]);
                }
            }
#pragma unroll
            for (int x = 0; x < 4; x++)
#pragma unroll
                for (int y = 0; y < 4; y++)
                    sH1[(et * 4 + x) * 68 + jt * 4 + y] = gelu_f(acc[x][y] * isr);
        }
        __syncthreads();

        // ---- stage 2: H2 = gelu(H1 @ W1 * isf)   (32e x 64j, K=64) ----
        {
            float acc[4][4];
#pragma unroll
            for (int x = 0; x < 4; x++)
#pragma unroll
                for (int y = 0; y < 4; y++) acc[x][y] = 0.f;
#pragma unroll 4
            for (int kk = 0; kk < FC; kk += 4) {
                float4 a[4];
#pragma unroll
                for (int x = 0; x < 4; x++)
                    a[x] = *(const float4*)&sH1[(et * 4 + x) * 68 + kk];
                float4 b0 = *(const float4*)&sW1v[jt * 260 + (kk + 0) * 4];
                float4 b1 = *(const float4*)&sW1v[jt * 260 + (kk + 1) * 4];
                float4 b2 = *(const float4*)&sW1v[jt * 260 + (kk + 2) * 4];
                float4 b3 = *(const float4*)&sW1v[jt * 260 + (kk + 3) * 4];
#pragma unroll
                for (int x = 0; x < 4; x++) {
                    acc[x][0] = fmaf(a[x].x, b0.x, fmaf(a[x].y, b1.x, fmaf(a[x].z, b2.x, fmaf(a[x].w, b3.x, acc[x][0]))));
                    acc[x][1] = fmaf(a[x].x, b0.y, fmaf(a[x].y, b1.y, fmaf(a[x].z, b2.y, fmaf(a[x].w, b3.y, acc[x][1]))));
                    acc[x][2] = fmaf(a[x].x, b0.z, fmaf(a[x].y, b1.z, fmaf(a[x].z, b2.z, fmaf(a[x].w, b3.z, acc[x][2]))));
                    acc[x][3] = fmaf(a[x].x, b0.w, fmaf(a[x].y, b1.w, fmaf(a[x].z, b2.w, fmaf(a[x].w, b3.w, acc[x][3]))));
                }
            }
#pragma unroll
            for (int x = 0; x < 4; x++)
#pragma unroll
                for (int y = 0; y < 4; y++)
                    sH2[(et * 4 + x) * 68 + jt * 4 + y] = gelu_f(acc[x][y] * isf);
        }
        __syncthreads();

        // ---- stage 3: W = H2 @ [wp0|wp1|wp2|wp3] * isf   (32e x 128m, K=64) ----
        {
            float acc[4][8];
#pragma unroll
            for (int x = 0; x < 4; x++)
#pragma unroll
                for (int y = 0; y < 8; y++) acc[x][y] = 0.f;
#pragma unroll 4
            for (int kk = 0; kk < FC; kk += 4) {
                float4 a[4];
#pragma unroll
                for (int x = 0; x < 4; x++)
                    a[x] = *(const float4*)&sH2[(et * 4 + x) * 68 + kk];
#pragma unroll
                for (int dk = 0; dk < 4; dk++) {
                    float4 c0 = *(const float4*)&sWPv[jt * 516 + (kk + dk) * 8];
                    float4 c1 = *(const float4*)&sWPv[jt * 516 + (kk + dk) * 8 + 4];
#pragma unroll
                    for (int x = 0; x < 4; x++) {
                        float av = (dk == 0) ? a[x].x : (dk == 1) ? a[x].y : (dk == 2) ? a[x].z : a[x].w;
                        acc[x][0] = fmaf(av, c0.x, acc[x][0]);
                        acc[x][1] = fmaf(av, c0.y, acc[x][1]);
                        acc[x][2] = fmaf(av, c0.z, acc[x][2]);
                        acc[x][3] = fmaf(av, c0.w, acc[x][3]);
                        acc[x][4] = fmaf(av, c1.x, acc[x][4]);
                        acc[x][5] = fmaf(av, c1.y, acc[x][5]);
                        acc[x][6] = fmaf(av, c1.z, acc[x][6]);
                        acc[x][7] = fmaf(av, c1.w, acc[x][7]);
                    }
                }
            }
#pragma unroll
            for (int x = 0; x < 4; x++) {
                float4 v0 = make_float4(acc[x][0] * isf, acc[x][1] * isf, acc[x][2] * isf, acc[x][3] * isf);
                float4 v1 = make_float4(acc[x][4] * isf, acc[x][5] * isf, acc[x][6] * isf, acc[x][7] * isf);
                *(float4*)&sWW[(et * 4 + x) * 132 + jt * 8]     = v0;
                *(float4*)&sWW[(et * 4 + x) * 132 + jt * 8 + 4] = v1;
            }
        }
        __syncthreads();

        // ---- stage 4: tensor product + v4-red scatter (uses prefetched gathers) ----
        {
            float e0v[8];
            e0v[0] = F0a.x; e0v[1] = F0a.y; e0v[2] = F0a.z; e0v[3] = F0a.w;
            e0v[4] = F0b.x; e0v[5] = F0b.y; e0v[6] = F0b.z; e0v[7] = F0b.w;
            float e1v[24];
#pragma unroll
            for (int i = 0; i < 6; i++) {
                e1v[4 * i + 0] = F1[i].x; e1v[4 * i + 1] = F1[i].y;
                e1v[4 * i + 2] = F1[i].z; e1v[4 * i + 3] = F1[i].w;
            }
            float w0v[8], w1v[8], w2v[8], w3v[8];
#pragma unroll
            for (int x = 0; x < 8; x += 4) {
                float4 v;
                v = *(const float4*)&sWW[e4 * 132 + 0  + u0 + x]; w0v[x] = v.x; w0v[x+1] = v.y; w0v[x+2] = v.z; w0v[x+3] = v.w;
                v = *(const float4*)&sWW[e4 * 132 + 32 + u0 + x]; w1v[x] = v.x; w1v[x+1] = v.y; w1v[x+2] = v.z; w1v[x+3] = v.w;
                v = *(const float4*)&sWW[e4 * 132 + 64 + u0 + x]; w2v[x] = v.x; w2v[x+1] = v.y; w2v[x+2] = v.z; w2v[x+3] = v.w;
                v = *(const float4*)&sWW[e4 * 132 + 96 + u0 + x]; w3v[x] = v.x; w3v[x+1] = v.y; w3v[x+2] = v.z; w3v[x+3] = v.w;
            }
            const float inn = 0.25f;                       // 1/sqrt(16)
            const float k3  = 0.5773502691896258f * 0.25f; // INV_SQRT3 * inn
            float p0[8], p3[8], p1[24], p2[24];
#pragma unroll
            for (int x = 0; x < 8; x++) {
                float e0u = e0v[x];
                float ex = e1v[3 * x + 0], ey = e1v[3 * x + 1], ez = e1v[3 * x + 2];
                p0[x] = w0v[x] * e0u * s0 * inn;
                p3[x] = w3v[x] * (ex * s1x + ey * s1y + ez * s1z) * k3;
                float w1e = w1v[x] * e0u * inn;
                p1[3 * x + 0] = w1e * s1x; p1[3 * x + 1] = w1e * s1y; p1[3 * x + 2] = w1e * s1z;
                float w2s = w2v[x] * s0 * inn;
                p2[3 * x + 0] = w2s * ex; p2[3 * x + 1] = w2s * ey; p2[3 * x + 2] = w2s * ez;
            }
            float* n0a = &g_n0[dst * 64 + u0];
            red_add_v4(n0a,     p0[0], p0[1], p0[2], p0[3]);
            red_add_v4(n0a + 4, p0[4], p0[5], p0[6], p0[7]);
            float* n0b = &g_n0[dst * 64 + 32 + u0];
            red_add_v4(n0b,     p3[0], p3[1], p3[2], p3[3]);
            red_add_v4(n0b + 4, p3[4], p3[5], p3[6], p3[7]);
            float* n1a = &g_n1[dst * 192 + u0 * 3];
#pragma unroll
            for (int i = 0; i < 6; i++)
                red_add_v4(n1a + 4 * i, p1[4 * i], p1[4 * i + 1], p1[4 * i + 2], p1[4 * i + 3]);
            float* n1b = &g_n1[dst * 192 + 96 + u0 * 3];
#pragma unroll
            for (int i = 0; i < 6; i++)
                red_add_v4(n1b + 4 * i, p2[4 * i], p2[4 * i + 1], p2[4 * i + 2], p2[4 * i + 3]);
        }
    }
}

// ---------------- kernel 3: output transform ----------------
__global__ __launch_bounds__(128) void output_kernel(
    const float* __restrict__ Wout0, const float* __restrict__ Wout1,
    float* __restrict__ out)
{
    __shared__ float sW0[FC * MUL], sW1[FC * MUL];
    __shared__ float sN0[4][64];
    __shared__ float sN1[4][192];
    int t = threadIdx.x;
    for (int i = t; i < FC * MUL; i += 128) { sW0[i] = Wout0[i]; sW1[i] = Wout1[i]; }
    int node0 = blockIdx.x * 4;
    for (int i = t; i < 4 * 64; i += 128)  sN0[i / 64][i % 64]   = g_n0[node0 * 64 + i];
    for (int i = t; i < 4 * 192; i += 128) sN1[i / 192][i % 192] = g_n1[node0 * 192 + i];
    __syncthreads();

    int ni = t >> 5, j = t & 31;
    int n = node0 + ni;
    float c0 = 0.f, c1x = 0.f, c1y = 0.f, c1z = 0.f;
#pragma unroll
    for (int u = 0; u < FC; u++) {
        float w0 = sW0[u * 32 + j], w1 = sW1[u * 32 + j];
        c0  += sN0[ni][u] * w0;
        c1x += sN1[ni][u * 3 + 0] * w1;
        c1y += sN1[ni][u * 3 + 1] * w1;
        c1z += sN1[ni][u * 3 + 2] * w1;
    }
    const float i2m = 0.125f; // 1/sqrt(64)
    const float cc = 0.9238795325112867f;  // cos(pi/8)
    const float ss = 0.3826834323650898f;  // sin(pi/8)
    int vb = (n * 32 + j) * 3;
    float o0  = cc * g_self0[n * 32 + j] + ss * c0 * i2m;
    float o1x = cc * g_self1[vb + 0] + ss * c1x * i2m;
    float o1y = cc * g_self1[vb + 1] + ss * c1y * i2m;
    float o1z = cc * g_self1[vb + 2] + ss * c1z * i2m;
    out[n * 128 + j] = o0;
    out[n * 128 + 32 + j * 3 + 0] = o1x;
    out[n * 128 + 32 + j * 3 + 1] = o1y;
    out[n * 128 + 32 + j * 3 + 2] = o1z;
}

// ---------------- host launcher ----------------
extern "C" void kernel_launch(void* const* d_in, const int* in_sizes, int n_in,
                              void* d_out, int out_size)
{
    const float* node_s      = (const float*)d_in[0];
    const float* node_v      = (const float*)d_in[1];
    const float* sh0         = (const float*)d_in[2];
    const float* sh1         = (const float*)d_in[3];
    const float* edge_scalar = (const float*)d_in[4];
    const int*   edge_src    = (const int*)d_in[5];
    const int*   edge_dst    = (const int*)d_in[6];
    const float* W_feat0     = (const float*)d_in[7];
    const float* W_self0     = (const float*)d_in[8];
    const float* W_feat1     = (const float*)d_in[9];
    const float* W_self1     = (const float*)d_in[10];
    const float* mlp_w0      = (const float*)d_in[11];
    const float* mlp_w1      = (const float*)d_in[12];
    const float* wp0         = (const float*)d_in[13];
    const float* wp1         = (const float*)d_in[14];
    const float* wp2         = (const float*)d_in[15];
    const float* wp3         = (const float*)d_in[16];
    const float* W_out0      = (const float*)d_in[17];
    const float* W_out1      = (const float*)d_in[18];
    float* out = (float*)d_out;

    cudaFuncSetAttribute(edge_kernel, cudaFuncAttributeMaxDynamicSharedMemorySize,
                         EDGE_SMEM_BYTES);

    zero_acc_kernel<<<(N_NODES * 48 + 255) / 256, 256>>>();

    node_transform_kernel<<<N_NODES / 4, 128>>>(node_s, node_v,
                                                W_feat0, W_self0, W_feat1, W_self1);

    edge_kernel<<<EDGE_BLOCKS, 128, EDGE_SMEM_BYTES>>>(
        sh0, sh1, edge_scalar, edge_src, edge_dst,
        mlp_w0, mlp_w1, wp0, wp1, wp2, wp3);

    output_kernel<<<N_NODES / 4, 128>>>(W_out0, W_out1, out);
}